// round 7
// baseline (speedup 1.0000x reference)
#include <cuda_runtime.h>
#include <cuda_fp16.h>

#define TT 256
typedef unsigned int u32; typedef unsigned long long u64; typedef unsigned short u16;

// prepacked: [mat 0..3][rank 0..3][k 0..127][u 0..31][gate 0..3] half2(Wih,Whh)
__device__ __align__(16) __half2 g_W[4 * 4 * 128 * 128];
__device__ __align__(16) __half2 g_OWs[4 * 128 * 32];   // [p][uu][d] = (ow,ow)
__device__ float g_b[4][512];

__global__ void prep_kernel(
    const float* __restrict__ eW0, const float* __restrict__ eU0,
    const float* __restrict__ ebi0, const float* __restrict__ ebh0,
    const float* __restrict__ eW1, const float* __restrict__ eU1,
    const float* __restrict__ ebi1, const float* __restrict__ ebh1,
    const float* __restrict__ dW0, const float* __restrict__ dU0,
    const float* __restrict__ dbi0, const float* __restrict__ dbh0,
    const float* __restrict__ dW1, const float* __restrict__ dU1,
    const float* __restrict__ dbi1, const float* __restrict__ dbh1,
    const float* __restrict__ oW)
{
    int idx = blockIdx.x * 512 + threadIdx.x;            // 0..262143
    int mat = idx >> 16, rem = idx & 65535;
    int p = rem >> 14, rem2 = rem & 16383;
    int k = rem2 >> 7, rem3 = rem2 & 127;
    int u = rem3 >> 2, g = rem3 & 3;
    int src = (g * 128 + p * 32 + u) * 128 + k;
    const float *W, *U;
    if (mat == 0)      { W = eW0; U = eU0; }
    else if (mat == 1) { W = eW1; U = eU1; }
    else if (mat == 2) { W = dW0; U = dU0; }
    else               { W = dW1; U = dU1; }
    g_W[idx] = __floats2half2_rn(W[src], U[src]);
    if (idx < 16384) {
        int pp = idx >> 12, uu = (idx >> 5) & 127, d = idx & 31;
        float v = oW[(pp * 32 + d) * 128 + uu];
        g_OWs[idx] = __floats2half2_rn(v, v);
    }
    if (idx < 512) {
        g_b[0][idx] = ebi0[idx] + ebh0[idx];
        g_b[1][idx] = ebi1[idx] + ebh1[idx];
        g_b[2][idx] = dbi0[idx] + dbh0[idx];
        g_b[3][idx] = dbi1[idx] + dbh1[idx];
    }
}

__device__ __forceinline__ float sigf(float v)   { return 1.0f / (1.0f + __expf(-v)); }
__device__ __forceinline__ float tanhfa(float v) { return 1.0f - 2.0f / (__expf(2.0f * v) + 1.0f); }

__device__ __forceinline__ void spill(u64& acc, __half2 a) {
    float lo = __low2float(a), hi = __high2float(a);
    u64 q;
    asm("mov.b64 %0, {%1,%2};" : "=l"(q) : "f"(lo), "f"(hi));
    asm("add.rn.f32x2 %0, %1, %2;" : "=l"(acc) : "l"(acc), "l"(q));
}

// smem byte offsets
#define SM_W0 0
#define SM_W1 65536
#define SM_X0 131072u
#define SM_X1 147456u
#define SM_OW 163840u
#define SM_TOTAL 180224

#define CBAR() do { asm volatile("barrier.cluster.arrive.aligned;" ::: "memory"); \
                    asm volatile("barrier.cluster.wait.aligned;"   ::: "memory"); } while (0)

__device__ __forceinline__ void bc4(const u32* dsm, u32 off, u16 v) {
#pragma unroll
    for (int r = 0; r < 4; r++)
        asm volatile("st.shared::cluster.u16 [%0], %1;" :: "r"(dsm[r] + off), "h"(v) : "memory");
}

// 16 partial gate sums (4 rows x 4 gates) over this thread's k-half.
__device__ __forceinline__ void gemm_slice(
    const char* smem, u32 woff, u32 xoff, int u, int rg, int s, float* sm16)
{
    const uint4* W = (const uint4*)(smem + woff) + (s * 64) * 32 + u;
    const uint4* X = (const uint4*)(smem + xoff) + (s * 64) * 4 + rg;
    u64 A[16];
#pragma unroll
    for (int i = 0; i < 16; i++) A[i] = 0;
#pragma unroll
    for (int c = 0; c < 4; c++) {
        __half2 a[16];
#pragma unroll
        for (int i = 0; i < 16; i++) a[i] = __float2half2_rn(0.f);
#pragma unroll
        for (int m = 0; m < 16; m++) {
            uint4 wq = W[(c * 16 + m) * 32];
            uint4 xq = X[(c * 16 + m) * 4];
            __half2 w0 = *(__half2*)&wq.x, w1 = *(__half2*)&wq.y;
            __half2 w2 = *(__half2*)&wq.z, w3 = *(__half2*)&wq.w;
            __half2 x0 = *(__half2*)&xq.x, x1 = *(__half2*)&xq.y;
            __half2 x2 = *(__half2*)&xq.z, x3 = *(__half2*)&xq.w;
            a[0]  = __hfma2(w0, x0, a[0]);  a[1]  = __hfma2(w1, x0, a[1]);
            a[2]  = __hfma2(w2, x0, a[2]);  a[3]  = __hfma2(w3, x0, a[3]);
            a[4]  = __hfma2(w0, x1, a[4]);  a[5]  = __hfma2(w1, x1, a[5]);
            a[6]  = __hfma2(w2, x1, a[6]);  a[7]  = __hfma2(w3, x1, a[7]);
            a[8]  = __hfma2(w0, x2, a[8]);  a[9]  = __hfma2(w1, x2, a[9]);
            a[10] = __hfma2(w2, x2, a[10]); a[11] = __hfma2(w3, x2, a[11]);
            a[12] = __hfma2(w0, x3, a[12]); a[13] = __hfma2(w1, x3, a[13]);
            a[14] = __hfma2(w2, x3, a[14]); a[15] = __hfma2(w3, x3, a[15]);
        }
#pragma unroll
        for (int i = 0; i < 16; i++) spill(A[i], a[i]);
    }
#pragma unroll
    for (int i = 0; i < 16; i++) {
        float lo, hi;
        asm("mov.b64 {%0,%1}, %2;" : "=f"(lo), "=f"(hi) : "l"(A[i]));
        sm16[i] = lo + hi;
    }
}

__device__ __forceinline__ void stage_w(char* smem, int mat, int p, int tid) {
    const uint4* src = (const uint4*)g_W + (mat * 4 + p) * 4096;
    uint4* dst = (uint4*)(smem + (mat & 1) * 65536);
#pragma unroll 4
    for (int i = tid; i < 4096; i += 256) dst[i] = src[i];
}

__global__ void __launch_bounds__(256, 1) __cluster_dims__(4, 1, 1)
lstm_main(const float* __restrict__ x, const float* __restrict__ out_b,
          float* __restrict__ out)
{
    extern __shared__ __align__(16) char smem[];
    const int tid = threadIdx.x;
    const int p   = blockIdx.x & 3;
    const int bg  = (blockIdx.x >> 2) * 16;
    const int rg  = tid >> 6;
    const int u   = (tid >> 1) & 31;
    const int s   = tid & 1;
    const int ug  = p * 32 + u;
    const int rA  = rg * 4 + 2 * s;           // act rows rA, rA+1
    const int xr  = tid & 15, xd = tid >> 4;  // x staging: row, dim-octet

    u32 sb = (u32)__cvta_generic_to_shared(smem);
    u32 dsm[4];
#pragma unroll
    for (int r = 0; r < 4; r++)
        asm("mapa.shared::cluster.u32 %0, %1, %2;" : "=r"(dsm[r]) : "r"(sb), "r"(r));

    // ---- init: weights E0/E1, zero xh, x(0), biases ----
    stage_w(smem, 0, p, tid);
    stage_w(smem, 1, p, tid);
    for (int i = tid; i < 2048; i += 256) *(uint4*)(smem + SM_X0 + i * 16) = make_uint4(0,0,0,0);
    __syncthreads();
    {
        const float* xp = x + ((size_t)(bg + xr) * TT + 0) * 128 + xd * 8;
        float4 a = *(const float4*)xp, b = *(const float4*)(xp + 4);
#pragma unroll
        for (int e = 0; e < 8; e++) {
            float v = e < 4 ? ((const float*)&a)[e] : ((const float*)&b)[e - 4];
            *(u16*)(smem + SM_X0 + (((xd * 8 + e) * 16 + xr) << 2)) = __half_as_ushort(__float2half(v));
        }
    }
    float bi0[4], bi1[4];
#pragma unroll
    for (int g = 0; g < 4; g++) { bi0[g] = g_b[0][g * 128 + ug]; bi1[g] = g_b[1][g * 128 + ug]; }
    float c0A = 0.f, c0B = 0.f, c1A = 0.f, c1B = 0.f, h1A = 0.f, h1B = 0.f, obv = 0.f;
    CBAR();

    for (int tt = 0; tt < 512; tt++) {
        const bool dec = tt >= 256;
        const int t = tt & 255;
        const u32 pt = (u32)(t & 1), pn = pt ^ 1u;

        if (tt == 256) {            // ---- phase switch ----
            CBAR();                 // flush all encoder writes
            for (int i = tid; i < 2048; i += 256) *(uint4*)(smem + SM_X0 + i * 16) = make_uint4(0,0,0,0);
            stage_w(smem, 2, p, tid);
            stage_w(smem, 3, p, tid);
            {   // OW slice
                const uint4* src = (const uint4*)g_OWs + p * 1024;
                uint4* dst = (uint4*)(smem + SM_OW);
                for (int i = tid; i < 1024; i += 256) dst[i] = src[i];
            }
#pragma unroll
            for (int g = 0; g < 4; g++) { bi0[g] = g_b[2][g * 128 + ug]; bi1[g] = g_b[3][g * 128 + ug]; }
            obv = out_b[ug];
            c0A = c0B = c1A = c1B = 0.f;
            __syncthreads();
            CBAR();
            // x0 = final encoder h1 (held in regs) -> xh0[par 0].x, all ranks
            bc4(dsm, SM_X0 + ((u32)(ug * 16 + rA)     << 2), __half_as_ushort(__float2half(h1A)));
            bc4(dsm, SM_X0 + ((u32)(ug * 16 + rA + 1) << 2), __half_as_ushort(__float2half(h1B)));
            CBAR();
        }

        // x prefetch (encoder)
        float4 xa, xb;
        if (!dec && t < 255) {
            const float* xp = x + ((size_t)(bg + xr) * TT + (t + 1)) * 128 + xd * 8;
            xa = *(const float4*)xp; xb = *(const float4*)(xp + 4);
        }

        float sm16[16];
        // ---------------- layer 0 ----------------
        gemm_slice(smem, SM_W0, SM_X0 + pt * 8192, u, rg, s, sm16);
#pragma unroll
        for (int i = 0; i < 16; i++) sm16[i] += __shfl_xor_sync(0xffffffffu, sm16[i], 1);
        {
            float gA[4], gB[4];
#pragma unroll
            for (int g = 0; g < 4; g++) { gA[g] = (s ? sm16[8 + g] : sm16[g]) + bi0[g];
                                          gB[g] = (s ? sm16[12 + g] : sm16[4 + g]) + bi0[g]; }
            c0A = sigf(gA[1]) * c0A + sigf(gA[0]) * tanhfa(gA[2]);
            c0B = sigf(gB[1]) * c0B + sigf(gB[0]) * tanhfa(gB[2]);
            float hA = sigf(gA[3]) * tanhfa(c0A), hB = sigf(gB[3]) * tanhfa(c0B);
            u16 ha = __half_as_ushort(__float2half(hA)), hb = __half_as_ushort(__float2half(hB));
            u32 wA = (u32)(ug * 16 + rA) << 2, wB = (u32)(ug * 16 + rA + 1) << 2;
            bc4(dsm, SM_X1 + pt * 8192 + wA, ha);       // layer-1 input .x
            bc4(dsm, SM_X1 + pt * 8192 + wB, hb);
            bc4(dsm, SM_X0 + pn * 8192 + wA + 2, ha);   // next-step recurrent .y
            bc4(dsm, SM_X0 + pn * 8192 + wB + 2, hb);
        }
        if (!dec && t < 255) {
            char* d = smem + SM_X0 + pn * 8192;
#pragma unroll
            for (int e = 0; e < 8; e++) {
                float v = e < 4 ? ((const float*)&xa)[e] : ((const float*)&xb)[e - 4];
                *(u16*)(d + (((xd * 8 + e) * 16 + xr) << 2)) = __half_as_ushort(__float2half(v));
            }
        }
        CBAR();

        // ---------------- layer 1 ----------------
        gemm_slice(smem, SM_W1, SM_X1 + pt * 8192, u, rg, s, sm16);
#pragma unroll
        for (int i = 0; i < 16; i++) sm16[i] += __shfl_xor_sync(0xffffffffu, sm16[i], 1);
        {
            float gA[4], gB[4];
#pragma unroll
            for (int g = 0; g < 4; g++) { gA[g] = (s ? sm16[8 + g] : sm16[g]) + bi1[g];
                                          gB[g] = (s ? sm16[12 + g] : sm16[4 + g]) + bi1[g]; }
            c1A = sigf(gA[1]) * c1A + sigf(gA[0]) * tanhfa(gA[2]);
            c1B = sigf(gB[1]) * c1B + sigf(gB[0]) * tanhfa(gB[2]);
            h1A = sigf(gA[3]) * tanhfa(c1A); h1B = sigf(gB[3]) * tanhfa(c1B);
            u16 ha = __half_as_ushort(__float2half(h1A)), hb = __half_as_ushort(__float2half(h1B));
            u32 wA = (u32)(ug * 16 + rA) << 2, wB = (u32)(ug * 16 + rA + 1) << 2;
            bc4(dsm, SM_X1 + pn * 8192 + wA + 2, ha);   // h1 recurrent .y
            bc4(dsm, SM_X1 + pn * 8192 + wB + 2, hb);
            if (dec) {
                bc4(dsm, SM_X0 + pn * 8192 + wA, ha);   // feedback input .x
                bc4(dsm, SM_X0 + pn * 8192 + wB, hb);
            }
        }
        if (dec) {
            CBAR();
            // projection: out[rowA/B, t, ug] from h1 (xh1[pn].y) x OW slice
            u64 P = 0; __half2 pa = __float2half2_rn(0.f);
            const char* xb1 = smem + SM_X1 + pn * 8192;
#pragma unroll 8
            for (int uu = 0; uu < 128; uu++) {
                uint2 wp = *(const uint2*)(xb1 + ((uu * 16 + rA) << 2));
                u32 hp;
                asm("prmt.b32 %0, %1, %2, 0x7632;" : "=r"(hp) : "r"(wp.x), "r"(wp.y));
                __half2 ow = *(const __half2*)(smem + SM_OW + ((uu * 32 + u) << 2));
                pa = __hfma2(ow, *(__half2*)&hp, pa);
                if ((uu & 15) == 15) { spill(P, pa); pa = __float2half2_rn(0.f); }
            }
            float oA, oB;
            asm("mov.b64 {%0,%1}, %2;" : "=f"(oA), "=f"(oB) : "l"(P));
            out[((size_t)(bg + rA) * TT + t) * 128 + ug]     = oA + obv;
            out[((size_t)(bg + rA + 1) * TT + t) * 128 + ug] = oB + obv;
        }
    }
}

extern "C" void kernel_launch(void* const* d_in, const int* in_sizes, int n_in,
                              void* d_out, int out_size)
{
    cudaFuncSetAttribute(lstm_main, cudaFuncAttributeMaxDynamicSharedMemorySize, SM_TOTAL);
    prep_kernel<<<512, 512>>>(
        (const float*)d_in[1],  (const float*)d_in[2],  (const float*)d_in[3],
        (const float*)d_in[4],  (const float*)d_in[5],  (const float*)d_in[6],
        (const float*)d_in[7],  (const float*)d_in[8],  (const float*)d_in[9],
        (const float*)d_in[10], (const float*)d_in[11], (const float*)d_in[12],
        (const float*)d_in[13], (const float*)d_in[14], (const float*)d_in[15],
        (const float*)d_in[16], (const float*)d_in[17]);
    lstm_main<<<128, 256, SM_TOTAL>>>((const float*)d_in[0], (const float*)d_in[18],
                                      (float*)d_out);
}

// round 9
// speedup vs baseline: 1.0081x; 1.0081x over previous
#include <cuda_runtime.h>
#include <cuda_fp16.h>

#define TT 256
typedef unsigned int u32; typedef unsigned long long u64; typedef unsigned short u16;

// [mat 0..3][ih 0..1][p 0..3][kk 0..63][u 0..31][gate 0..3] half2(w_2kk, w_2kk+1)
__device__ __align__(16) __half2 g_W[262144];
__device__ __align__(16) __half2 g_OWp[8192];    // [p][kk][u]
__device__ float g_b[4][512];

__global__ void prep_kernel(
    const float* __restrict__ eW0, const float* __restrict__ eU0,
    const float* __restrict__ ebi0, const float* __restrict__ ebh0,
    const float* __restrict__ eW1, const float* __restrict__ eU1,
    const float* __restrict__ ebi1, const float* __restrict__ ebh1,
    const float* __restrict__ dW0, const float* __restrict__ dU0,
    const float* __restrict__ dbi0, const float* __restrict__ dbh0,
    const float* __restrict__ dW1, const float* __restrict__ dU1,
    const float* __restrict__ dbi1, const float* __restrict__ dbh1,
    const float* __restrict__ oW)
{
    int idx = blockIdx.x * 512 + threadIdx.x;        // 0..262143
    int g = idx & 3, u = (idx >> 2) & 31, kk = (idx >> 7) & 63;
    int p = (idx >> 13) & 3, ih = (idx >> 15) & 1, mat = (idx >> 16) & 3;
    int sel = mat * 2 + ih;
    const float* M = (sel==0)?eW0:(sel==1)?eU0:(sel==2)?eW1:(sel==3)?eU1:
                     (sel==4)?dW0:(sel==5)?dU0:(sel==6)?dW1:dU1;
    int j = g * 128 + p * 32 + u;
    g_W[idx] = __floats2half2_rn(M[j*128 + 2*kk], M[j*128 + 2*kk + 1]);
    if (idx < 8192) {
        int d = (idx >> 11) * 32 + (idx & 31);
        int k2 = (idx >> 5) & 63;
        g_OWp[idx] = __floats2half2_rn(oW[d*128 + 2*k2], oW[d*128 + 2*k2 + 1]);
    }
    if (idx < 512) {
        g_b[0][idx] = ebi0[idx] + ebh0[idx];
        g_b[1][idx] = ebi1[idx] + ebh1[idx];
        g_b[2][idx] = dbi0[idx] + dbh0[idx];
        g_b[3][idx] = dbi1[idx] + dbh1[idx];
    }
}

__device__ __forceinline__ float sigf(float v)   { return 1.0f / (1.0f + __expf(-v)); }
__device__ __forceinline__ float tanhfa(float v) { return 1.0f - 2.0f / (__expf(2.0f * v) + 1.0f); }
__device__ __forceinline__ __half2 h2(u32 v) { return *(__half2*)&v; }
__device__ __forceinline__ u32 pk(float a, float b) {
    __half2 h = __floats2half2_rn(a, b); return *(u32*)&h;
}
__device__ __forceinline__ void spill(u64& acc, __half2 a) {
    float lo = __low2float(a), hi = __high2float(a);
    u64 q;
    asm("mov.b64 %0, {%1,%2};" : "=l"(q) : "f"(lo), "f"(hi));
    asm("add.rn.f32x2 %0, %1, %2;" : "=l"(acc) : "l"(acc), "l"(q));
}
__device__ __forceinline__ float fin2(u64 acc) {
    float lo, hi;
    asm("mov.b64 {%0,%1}, %2;" : "=f"(lo), "=f"(hi) : "l"(acc));
    return lo + hi;
}

// smem layout (bytes)
#define SW0I 0u
#define SW0H 32768u
#define SW1I 65536u
#define SW1H 98304u
#define SX   131072u   // X[2]  : [par][row][k] half (k-pairs as half2), 4KB/par
#define SH0  139264u
#define SH1  147456u
#define SOW  155648u
#define STOT 163840

#define CBAR() do { asm volatile("barrier.cluster.arrive.aligned;" ::: "memory"); \
                    asm volatile("barrier.cluster.wait.aligned;"   ::: "memory"); } while (0)

// scalar u16 store of own h to same offset in all 4 ranks (R7-proven primitive)
__device__ __forceinline__ void bc4(const u32* dsm, u32 off, u16 v) {
#pragma unroll
    for (int r = 0; r < 4; r++)
        asm volatile("st.shared::cluster.u16 [%0], %1;"
                     :: "r"(dsm[r] + off), "h"(v) : "memory");
}

__device__ __forceinline__ void stage_w(char* sm, int mat, int p, int tid) {
    const uint4* s0 = (const uint4*)g_W + ((mat*2+0)*4 + p) * 2048;
    const uint4* s1 = (const uint4*)g_W + ((mat*2+1)*4 + p) * 2048;
    uint4* d0 = (uint4*)(sm + (mat & 1) * 65536);
    uint4* d1 = (uint4*)(sm + (mat & 1) * 65536 + 32768);
#pragma unroll
    for (int i = 0; i < 4; i++) {
        d0[tid + i*512] = s0[tid + i*512];
        d1[tid + i*512] = s1[tid + i*512];
    }
}

// gates for (row, u): 4 accumulators, k-pair HFMA2, f32x2 spill every 4 kk
__device__ __forceinline__ void gemm_ru(const char* sm, u32 wI, u32 wH,
    u32 xo, u32 ho, int u, int row, float4* r)
{
    const uint4* wi = (const uint4*)(sm + wI) + u;
    const uint4* wh = (const uint4*)(sm + wH) + u;
    const uint4* xr = (const uint4*)(sm + xo) + row * 16;
    const uint4* hr = (const uint4*)(sm + ho) + row * 16;
    u64 A0 = 0, A1 = 0, A2 = 0, A3 = 0;
    const __half2 z = __float2half2_rn(0.f);
#pragma unroll 4
    for (int c = 0; c < 16; c++) {
        uint4 xq = xr[c], hq = hr[c];
        __half2 a0 = z, a1 = z, a2 = z, a3 = z;
#pragma unroll
        for (int m = 0; m < 4; m++) {
            uint4 wq = wi[(c*4 + m) * 32];
            uint4 vq = wh[(c*4 + m) * 32];
            __half2 xv = ((const __half2*)&xq)[m];
            __half2 hv = ((const __half2*)&hq)[m];
            a0 = __hfma2(h2(wq.x), xv, a0); a1 = __hfma2(h2(wq.y), xv, a1);
            a2 = __hfma2(h2(wq.z), xv, a2); a3 = __hfma2(h2(wq.w), xv, a3);
            a0 = __hfma2(h2(vq.x), hv, a0); a1 = __hfma2(h2(vq.y), hv, a1);
            a2 = __hfma2(h2(vq.z), hv, a2); a3 = __hfma2(h2(vq.w), hv, a3);
        }
        spill(A0, a0); spill(A1, a1); spill(A2, a2); spill(A3, a3);
    }
    r->x = fin2(A0); r->y = fin2(A1); r->z = fin2(A2); r->w = fin2(A3);
}

__global__ void __launch_bounds__(512, 1) __cluster_dims__(4, 1, 1)
lstm_main(const float* __restrict__ x, const float* __restrict__ out_b,
          float* __restrict__ out)
{
    extern __shared__ __align__(16) char sm[];
    const int tid = threadIdx.x;
    const int u = tid & 31, row = tid >> 5;
    const int p  = blockIdx.x & 3;
    const int bg = (blockIdx.x >> 2) * 16;
    const u32 hoff = (u32)(row * 256 + p * 64 + u * 2);

    u32 sb = (u32)__cvta_generic_to_shared(sm);
    u32 dsm[4];
#pragma unroll
    for (int r = 0; r < 4; r++)
        asm("mapa.shared::cluster.u32 %0, %1, %2;" : "=r"(dsm[r]) : "r"(sb), "r"(r));

    stage_w(sm, 0, p, tid);
    stage_w(sm, 1, p, tid);
    if (tid < 256) {
        ((uint4*)(sm + SH0))[tid] = make_uint4(0,0,0,0);
        ((uint4*)(sm + SH1))[tid] = make_uint4(0,0,0,0);
        const float* xp = x + ((size_t)(bg + (tid >> 4)) * TT) * 128 + (tid & 15) * 8;
        float4 a = *(const float4*)xp, b = *(const float4*)(xp + 4);
        ((uint4*)(sm + SX))[tid] =
            make_uint4(pk(a.x,a.y), pk(a.z,a.w), pk(b.x,b.y), pk(b.z,b.w));
    }
    float bi0[4], bi1[4];
#pragma unroll
    for (int g = 0; g < 4; g++) {
        bi0[g] = g_b[0][g*128 + p*32 + u];
        bi1[g] = g_b[1][g*128 + p*32 + u];
    }
    float c0 = 0.f, c1 = 0.f;
    __syncthreads();
    CBAR();

    // -------------------- encoder: 1 CBAR per step --------------------
    for (int t = 0; t < TT; t++) {
        const u32 pt = (u32)(t & 1) * 4096u, pn = pt ^ 4096u;
        float4 xa, xb, r;
        const bool pre = (tid < 256) && (t < TT - 1);
        if (pre) {
            const float* xp = x + ((size_t)(bg + (tid >> 4)) * TT + t + 1) * 128 + (tid & 15) * 8;
            xa = *(const float4*)xp; xb = *(const float4*)(xp + 4);
        }
        gemm_ru(sm, SW0I, SW0H, SX + pt, SH0 + pt, u, row, &r);
        {
            float cn = sigf(r.y + bi0[1]) * c0 + sigf(r.x + bi0[0]) * tanhfa(r.z + bi0[2]);
            c0 = cn;
            float h = sigf(r.w + bi0[3]) * tanhfa(cn);
            bc4(dsm, SH0 + pn + hoff, __half_as_ushort(__float2half(h)));
        }
        if (pre)
            ((uint4*)(sm + SX + pn))[tid] =
                make_uint4(pk(xa.x,xa.y), pk(xa.z,xa.w), pk(xb.x,xb.y), pk(xb.z,xb.w));
        __syncthreads();
        CBAR();
        gemm_ru(sm, SW1I, SW1H, SH0 + pn, SH1 + pt, u, row, &r);
        {
            float cn = sigf(r.y + bi1[1]) * c1 + sigf(r.x + bi1[0]) * tanhfa(r.z + bi1[2]);
            c1 = cn;
            float h = sigf(r.w + bi1[3]) * tanhfa(cn);
            bc4(dsm, SH1 + pn + hoff, __half_as_ushort(__float2half(h)));
        }
        // SH1+pn is consumed only after next step's CBAR -> no barrier here
    }

    // -------------------- switch --------------------
    CBAR();                                   // final bc4(SH1+par0) visible
    if (tid < 256) {
        uint4 x0v = ((uint4*)(sm + SH1))[tid];         // final h1 (parity 0)
        ((uint4*)(sm + SX))[tid]  = x0v;               // decoder x0
        ((uint4*)(sm + SH0))[tid] = make_uint4(0,0,0,0);
        ((uint4*)(sm + SH1))[tid] = make_uint4(0,0,0,0);
    }
    stage_w(sm, 2, p, tid);
    stage_w(sm, 3, p, tid);
    ((uint4*)(sm + SOW))[tid] = ((const uint4*)g_OWp)[p * 512 + tid];
#pragma unroll
    for (int g = 0; g < 4; g++) {
        bi0[g] = g_b[2][g*128 + p*32 + u];
        bi1[g] = g_b[3][g*128 + p*32 + u];
    }
    const float obv = out_b[p * 32 + u];
    c0 = 0.f; c1 = 0.f;
    __syncthreads();

    // -------------------- decoder: 2 CBARs per step --------------------
    for (int t = 0; t < TT; t++) {
        const u32 pt = (u32)(t & 1) * 4096u, pn = pt ^ 4096u;
        float4 r;
        gemm_ru(sm, SW0I, SW0H, SX + pt, SH0 + pt, u, row, &r);
        {
            float cn = sigf(r.y + bi0[1]) * c0 + sigf(r.x + bi0[0]) * tanhfa(r.z + bi0[2]);
            c0 = cn;
            float h = sigf(r.w + bi0[3]) * tanhfa(cn);
            bc4(dsm, SH0 + pn + hoff, __half_as_ushort(__float2half(h)));
        }
        __syncthreads();
        CBAR();
        gemm_ru(sm, SW1I, SW1H, SH0 + pn, SH1 + pt, u, row, &r);
        {
            float cn = sigf(r.y + bi1[1]) * c1 + sigf(r.x + bi1[0]) * tanhfa(r.z + bi1[2]);
            c1 = cn;
            float h = sigf(r.w + bi1[3]) * tanhfa(cn);
            u16 hu = __half_as_ushort(__float2half(h));
            bc4(dsm, SH1 + pn + hoff, hu);     // h1 recurrent
            bc4(dsm, SX  + pn + hoff, hu);     // feedback input
        }
        __syncthreads();
        CBAR();
        {   // projection: out dim d = p*32+u
            u64 P = 0;
            const __half2* ow = (const __half2*)(sm + SOW) + u;
            const uint4* hx = (const uint4*)(sm + SX + pn) + row * 16;
            __half2 pa = __float2half2_rn(0.f);
#pragma unroll 4
            for (int c = 0; c < 16; c++) {
                uint4 hq = hx[c];
#pragma unroll
                for (int m = 0; m < 4; m++)
                    pa = __hfma2(ow[(c*4 + m) * 32], ((const __half2*)&hq)[m], pa);
                if ((c & 3) == 3) { spill(P, pa); pa = __float2half2_rn(0.f); }
            }
            out[((size_t)(bg + row) * TT + t) * 128 + p * 32 + u] = fin2(P) + obv;
        }
    }
}

extern "C" void kernel_launch(void* const* d_in, const int* in_sizes, int n_in,
                              void* d_out, int out_size)
{
    cudaFuncSetAttribute(lstm_main, cudaFuncAttributeMaxDynamicSharedMemorySize, STOT);
    prep_kernel<<<512, 512>>>(
        (const float*)d_in[1],  (const float*)d_in[2],  (const float*)d_in[3],
        (const float*)d_in[4],  (const float*)d_in[5],  (const float*)d_in[6],
        (const float*)d_in[7],  (const float*)d_in[8],  (const float*)d_in[9],
        (const float*)d_in[10], (const float*)d_in[11], (const float*)d_in[12],
        (const float*)d_in[13], (const float*)d_in[14], (const float*)d_in[15],
        (const float*)d_in[16], (const float*)d_in[17]);
    lstm_main<<<128, 512, STOT>>>((const float*)d_in[0], (const float*)d_in[18],
                                  (float*)d_out);
}

// round 10
// speedup vs baseline: 1.1773x; 1.1678x over previous
#include <cuda_runtime.h>
#include <cuda_fp16.h>

#define TT 256
typedef unsigned int u32; typedef unsigned long long u64; typedef unsigned short u16;

// [mat 0..3][ih 0..1][p 0..3][kk 0..63][u 0..31][gate 0..3] half2(w_2kk, w_2kk+1)
__device__ __align__(16) __half2 g_W[262144];
__device__ __align__(16) __half2 g_OWp[8192];    // [p][kk][u]
__device__ float g_b[4][512];

__global__ void prep_kernel(
    const float* __restrict__ eW0, const float* __restrict__ eU0,
    const float* __restrict__ ebi0, const float* __restrict__ ebh0,
    const float* __restrict__ eW1, const float* __restrict__ eU1,
    const float* __restrict__ ebi1, const float* __restrict__ ebh1,
    const float* __restrict__ dW0, const float* __restrict__ dU0,
    const float* __restrict__ dbi0, const float* __restrict__ dbh0,
    const float* __restrict__ dW1, const float* __restrict__ dU1,
    const float* __restrict__ dbi1, const float* __restrict__ dbh1,
    const float* __restrict__ oW)
{
    int idx = blockIdx.x * 512 + threadIdx.x;
    int g = idx & 3, u = (idx >> 2) & 31, kk = (idx >> 7) & 63;
    int p = (idx >> 13) & 3, ih = (idx >> 15) & 1, mat = (idx >> 16) & 3;
    int sel = mat * 2 + ih;
    const float* M = (sel==0)?eW0:(sel==1)?eU0:(sel==2)?eW1:(sel==3)?eU1:
                     (sel==4)?dW0:(sel==5)?dU0:(sel==6)?dW1:dU1;
    int j = g * 128 + p * 32 + u;
    g_W[idx] = __floats2half2_rn(M[j*128 + 2*kk], M[j*128 + 2*kk + 1]);
    if (idx < 8192) {
        int d = (idx >> 11) * 32 + (idx & 31);
        int k2 = (idx >> 5) & 63;
        g_OWp[idx] = __floats2half2_rn(oW[d*128 + 2*k2], oW[d*128 + 2*k2 + 1]);
    }
    if (idx < 512) {
        g_b[0][idx] = ebi0[idx] + ebh0[idx];
        g_b[1][idx] = ebi1[idx] + ebh1[idx];
        g_b[2][idx] = dbi0[idx] + dbh0[idx];
        g_b[3][idx] = dbi1[idx] + dbh1[idx];
    }
}

__device__ __forceinline__ float sigf(float v)   { return 1.0f / (1.0f + __expf(-v)); }
__device__ __forceinline__ float tanhfa(float v) { return 1.0f - 2.0f / (__expf(2.0f * v) + 1.0f); }
__device__ __forceinline__ __half2 h2(u32 v) { return *(__half2*)&v; }
__device__ __forceinline__ u32 pk(float a, float b) {
    __half2 h = __floats2half2_rn(a, b); return *(u32*)&h;
}
__device__ __forceinline__ void spill(u64& acc, __half2 a) {
    float lo = __low2float(a), hi = __high2float(a);
    u64 q;
    asm("mov.b64 %0, {%1,%2};" : "=l"(q) : "f"(lo), "f"(hi));
    asm("add.rn.f32x2 %0, %1, %2;" : "=l"(acc) : "l"(acc), "l"(q));
}
__device__ __forceinline__ float fin2(u64 acc) {
    float lo, hi;
    asm("mov.b64 {%0,%1}, %2;" : "=f"(lo), "=f"(hi) : "l"(acc));
    return lo + hi;
}

// xh buffers: 4KB, packed [sk(4)][rq(4)][kkl(16)][r4(4)] half2
// u32-word index for (k, row):
__device__ __forceinline__ u32 xh_word(int k, int row) {
    int kk = k >> 1;
    return (u32)(((((kk >> 4) * 4 + (row >> 2)) * 16 + (kk & 15)) * 4) + (row & 3));
}

#define SW0I 0u
#define SW0H 32768u
#define SW1I 65536u
#define SW1H 98304u
#define SX   131072u
#define SH0  139264u
#define SH1  147456u
#define SOW  155648u
#define SRED0 163840u
#define SRED1 188416u
#define STOT 212992

#define CBAR() do { asm volatile("barrier.cluster.arrive.aligned;" ::: "memory"); \
                    asm volatile("barrier.cluster.wait.aligned;"   ::: "memory"); } while (0)

__device__ __forceinline__ void bc4(const u32* dsm, u32 off, u16 v) {
#pragma unroll
    for (int r = 0; r < 4; r++)
        asm volatile("st.shared::cluster.u16 [%0], %1;"
                     :: "r"(dsm[r] + off), "h"(v) : "memory");
}

__device__ __forceinline__ void stage_w(char* sm, int mat, int p, int tid) {
    const uint4* s0 = (const uint4*)g_W + ((mat*2+0)*4 + p) * 2048;
    const uint4* s1 = (const uint4*)g_W + ((mat*2+1)*4 + p) * 2048;
    uint4* d0 = (uint4*)(sm + (mat & 1) * 65536);
    uint4* d1 = (uint4*)(sm + (mat & 1) * 65536 + 32768);
#pragma unroll
    for (int i = 0; i < 4; i++) {
        d0[tid + i*512] = s0[tid + i*512];
        d1[tid + i*512] = s1[tid + i*512];
    }
}

// 4 rows x 4 gates over k-quarter s. g16 order [gate][row].
__device__ __forceinline__ void gemm_r4(const char* sm, u32 wI, u32 wH,
    u32 xo, u32 ho, int u, int rg, int s, float* g16)
{
    const uint4* wi = (const uint4*)(sm + wI) + s*512 + u;
    const uint4* wh = (const uint4*)(sm + wH) + s*512 + u;
    const uint4* xr = (const uint4*)(sm + xo) + (s*4 + rg)*16;
    const uint4* hr = (const uint4*)(sm + ho) + (s*4 + rg)*16;
    u64 A[16];
#pragma unroll
    for (int i = 0; i < 16; i++) A[i] = 0;
#pragma unroll
    for (int c = 0; c < 4; c++) {
        __half2 a[16];
#pragma unroll
        for (int i = 0; i < 16; i++) a[i] = __float2half2_rn(0.f);
#pragma unroll
        for (int m = 0; m < 4; m++) {
            int kkl = c*4 + m;
            uint4 wq = wi[kkl*32];
            uint4 vq = wh[kkl*32];
            uint4 xq = xr[kkl];
            uint4 hq = hr[kkl];
#pragma unroll
            for (int r = 0; r < 4; r++) {
                __half2 xv = ((__half2*)&xq)[r];
                __half2 hv = ((__half2*)&hq)[r];
                a[r]    = __hfma2(h2(wq.x), xv, a[r]);
                a[4+r]  = __hfma2(h2(wq.y), xv, a[4+r]);
                a[8+r]  = __hfma2(h2(wq.z), xv, a[8+r]);
                a[12+r] = __hfma2(h2(wq.w), xv, a[12+r]);
                a[r]    = __hfma2(h2(vq.x), hv, a[r]);
                a[4+r]  = __hfma2(h2(vq.y), hv, a[4+r]);
                a[8+r]  = __hfma2(h2(vq.z), hv, a[8+r]);
                a[12+r] = __hfma2(h2(vq.w), hv, a[12+r]);
            }
        }
#pragma unroll
        for (int i = 0; i < 16; i++) spill(A[i], a[i]);
    }
#pragma unroll
    for (int i = 0; i < 16; i++) g16[i] = fin2(A[i]);
}

// s>0: store partials. s==0: reduce.
__device__ __forceinline__ void red_store(char* sm, u32 base, int u, int rg, int s, const float* g16) {
    float4* d = (float4*)(sm + base + (u32)(((s-1)*4 + rg)*2048) + (u32)u*16);
#pragma unroll
    for (int i = 0; i < 4; i++) d[i*32] = ((const float4*)g16)[i];
}
__device__ __forceinline__ void red_load(const char* sm, u32 base, int u, int rg, float* g16) {
#pragma unroll
    for (int ss = 0; ss < 3; ss++) {
        const float4* d = (const float4*)(sm + base + (u32)((ss*4 + rg)*2048) + (u32)u*16);
#pragma unroll
        for (int i = 0; i < 4; i++) {
            float4 v = d[i*32];
            g16[i*4+0] += v.x; g16[i*4+1] += v.y; g16[i*4+2] += v.z; g16[i*4+3] += v.w;
        }
    }
}

__global__ void __launch_bounds__(512, 1) __cluster_dims__(4, 1, 1)
lstm_main(const float* __restrict__ x, const float* __restrict__ out_b,
          float* __restrict__ out)
{
    extern __shared__ __align__(16) char sm[];
    const int tid = threadIdx.x;
    const int u = tid & 31, wid = tid >> 5;
    const int rg = wid & 3, s = wid >> 2;
    const int p  = blockIdx.x & 3;
    const int bg = (blockIdx.x >> 2) * 16;
    // bc4 base byte offset for h of unit ug=p*32+u, rows rg*4+r (r -> +4*r)
    const u32 hb = (u32)((((p*4 + rg)*16 + (u >> 1))*16) + (u & 1)*2);

    u32 sb = (u32)__cvta_generic_to_shared(sm);
    u32 dsm[4];
#pragma unroll
    for (int r = 0; r < 4; r++)
        asm("mapa.shared::cluster.u32 %0, %1, %2;" : "=r"(dsm[r]) : "r"(sb), "r"(r));

    stage_w(sm, 0, p, tid);
    stage_w(sm, 1, p, tid);
#pragma unroll
    for (int i = 0; i < 3; i++)
        ((uint4*)(sm + SX))[tid + i*512] = make_uint4(0,0,0,0);   // X,H0,H1 (24KB)
    __syncthreads();
    if (tid < 256) {   // stage x(t=0): row=tid>>4, oct=tid&15
        const int row = tid >> 4, oct = tid & 15;
        const float* xp = x + ((size_t)(bg + row) * TT) * 128 + oct * 8;
        float4 a = *(const float4*)xp, b = *(const float4*)(xp + 4);
        u32* X = (u32*)(sm + SX);
        X[xh_word(oct*8+0, row)] = pk(a.x, a.y);
        X[xh_word(oct*8+2, row)] = pk(a.z, a.w);
        X[xh_word(oct*8+4, row)] = pk(b.x, b.y);
        X[xh_word(oct*8+6, row)] = pk(b.z, b.w);
    }
    float bi0[4], bi1[4];
#pragma unroll
    for (int g = 0; g < 4; g++) {
        bi0[g] = g_b[0][g*128 + p*32 + u];
        bi1[g] = g_b[1][g*128 + p*32 + u];
    }
    float c0[4] = {0,0,0,0}, c1[4] = {0,0,0,0};
    float g16[16];
    __syncthreads();
    CBAR();

    // -------------------- encoder: 1 CBAR / step --------------------
    for (int t = 0; t < TT; t++) {
        const u32 pt = (u32)(t & 1) * 4096u, pn = pt ^ 4096u;
        float4 xa, xb;
        const bool pre = (tid < 256) && (t < TT - 1);
        if (pre) {
            const float* xp = x + ((size_t)(bg + (tid >> 4)) * TT + t + 1) * 128 + (tid & 15) * 8;
            xa = *(const float4*)xp; xb = *(const float4*)(xp + 4);
        }
        gemm_r4(sm, SW0I, SW0H, SX + pt, SH0 + pt, u, rg, s, g16);
        if (s) red_store(sm, SRED0, u, rg, s, g16);
        __syncthreads();
        if (!s) {
            red_load(sm, SRED0, u, rg, g16);
#pragma unroll
            for (int r = 0; r < 4; r++) {
                float cn = sigf(g16[4+r] + bi0[1]) * c0[r]
                         + sigf(g16[r]   + bi0[0]) * tanhfa(g16[8+r]  + bi0[2]);
                c0[r] = cn;
                float h = sigf(g16[12+r] + bi0[3]) * tanhfa(cn);
                bc4(dsm, SH0 + pn + hb + (u32)r*4, __half_as_ushort(__float2half(h)));
            }
        }
        if (pre) {
            const int row = tid >> 4, oct = tid & 15;
            u32* X = (u32*)(sm + SX + pn);
            X[xh_word(oct*8+0, row)] = pk(xa.x, xa.y);
            X[xh_word(oct*8+2, row)] = pk(xa.z, xa.w);
            X[xh_word(oct*8+4, row)] = pk(xb.x, xb.y);
            X[xh_word(oct*8+6, row)] = pk(xb.z, xb.w);
        }
        CBAR();
        gemm_r4(sm, SW1I, SW1H, SH0 + pn, SH1 + pt, u, rg, s, g16);
        if (s) red_store(sm, SRED1, u, rg, s, g16);
        __syncthreads();
        if (!s) {
            red_load(sm, SRED1, u, rg, g16);
#pragma unroll
            for (int r = 0; r < 4; r++) {
                float cn = sigf(g16[4+r] + bi1[1]) * c1[r]
                         + sigf(g16[r]   + bi1[0]) * tanhfa(g16[8+r]  + bi1[2]);
                c1[r] = cn;
                float h = sigf(g16[12+r] + bi1[3]) * tanhfa(cn);
                bc4(dsm, SH1 + pn + hb + (u32)r*4, __half_as_ushort(__float2half(h)));
            }
        }
    }

    // -------------------- switch --------------------
    CBAR();
    if (tid < 256) {   // x0 = final h1 (parity 0); zero parity-0 states
        uint4 x0v = ((uint4*)(sm + SH1))[tid];
        ((uint4*)(sm + SX))[tid]  = x0v;
        ((uint4*)(sm + SH0))[tid] = make_uint4(0,0,0,0);
        ((uint4*)(sm + SH1))[tid] = make_uint4(0,0,0,0);
    }
    stage_w(sm, 2, p, tid);
    stage_w(sm, 3, p, tid);
    ((uint4*)(sm + SOW))[tid] = ((const uint4*)g_OWp)[p * 512 + tid];
#pragma unroll
    for (int g = 0; g < 4; g++) {
        bi0[g] = g_b[2][g*128 + p*32 + u];
        bi1[g] = g_b[3][g*128 + p*32 + u];
    }
    const float obv = out_b[p * 32 + u];
#pragma unroll
    for (int r = 0; r < 4; r++) { c0[r] = 0.f; c1[r] = 0.f; }
    __syncthreads();

    // -------------------- decoder: 2 CBARs / step --------------------
    const int prow = wid;                 // projection row for this warp
    const u32 pbase = (u32)((prow >> 2) * 256 + (prow & 3) * 4);
    for (int t = 0; t < TT; t++) {
        const u32 pt = (u32)(t & 1) * 4096u, pn = pt ^ 4096u;
        gemm_r4(sm, SW0I, SW0H, SX + pt, SH0 + pt, u, rg, s, g16);
        if (s) red_store(sm, SRED0, u, rg, s, g16);
        __syncthreads();
        if (!s) {
            red_load(sm, SRED0, u, rg, g16);
#pragma unroll
            for (int r = 0; r < 4; r++) {
                float cn = sigf(g16[4+r] + bi0[1]) * c0[r]
                         + sigf(g16[r]   + bi0[0]) * tanhfa(g16[8+r]  + bi0[2]);
                c0[r] = cn;
                float h = sigf(g16[12+r] + bi0[3]) * tanhfa(cn);
                bc4(dsm, SH0 + pn + hb + (u32)r*4, __half_as_ushort(__float2half(h)));
            }
        }
        CBAR();
        gemm_r4(sm, SW1I, SW1H, SH0 + pn, SH1 + pt, u, rg, s, g16);
        if (s) red_store(sm, SRED1, u, rg, s, g16);
        __syncthreads();
        if (!s) {
            red_load(sm, SRED1, u, rg, g16);
#pragma unroll
            for (int r = 0; r < 4; r++) {
                float cn = sigf(g16[4+r] + bi1[1]) * c1[r]
                         + sigf(g16[r]   + bi1[0]) * tanhfa(g16[8+r]  + bi1[2]);
                c1[r] = cn;
                float h = sigf(g16[12+r] + bi1[3]) * tanhfa(cn);
                u16 hu = __half_as_ushort(__float2half(h));
                bc4(dsm, SH1 + pn + hb + (u32)r*4, hu);
                bc4(dsm, SX  + pn + hb + (u32)r*4, hu);
            }
        }
        CBAR();
        {   // projection: warp -> row prow, lane -> dim p*32+u
            u64 P = 0;
            __half2 pa = __float2half2_rn(0.f);
            const char* hx = sm + SX + pn + pbase;
            const __half2* ow = (const __half2*)(sm + SOW) + u;
#pragma unroll 4
            for (int kk = 0; kk < 64; kk++) {
                __half2 hv = *(const __half2*)(hx + (kk >> 4)*1024 + (kk & 15)*16);
                pa = __hfma2(ow[kk*32], hv, pa);
                if ((kk & 15) == 15) { spill(P, pa); pa = __float2half2_rn(0.f); }
            }
            out[((size_t)(bg + prow) * TT + t) * 128 + p * 32 + u] = fin2(P) + obv;
        }
    }
}

extern "C" void kernel_launch(void* const* d_in, const int* in_sizes, int n_in,
                              void* d_out, int out_size)
{
    cudaFuncSetAttribute(lstm_main, cudaFuncAttributeMaxDynamicSharedMemorySize, STOT);
    prep_kernel<<<512, 512>>>(
        (const float*)d_in[1],  (const float*)d_in[2],  (const float*)d_in[3],
        (const float*)d_in[4],  (const float*)d_in[5],  (const float*)d_in[6],
        (const float*)d_in[7],  (const float*)d_in[8],  (const float*)d_in[9],
        (const float*)d_in[10], (const float*)d_in[11], (const float*)d_in[12],
        (const float*)d_in[13], (const float*)d_in[14], (const float*)d_in[15],
        (const float*)d_in[16], (const float*)d_in[17]);
    lstm_main<<<128, 512, STOT>>>((const float*)d_in[0], (const float*)d_in[18],
                                  (float*)d_out);
}

// round 12
// speedup vs baseline: 1.1874x; 1.0086x over previous
#include <cuda_runtime.h>
#include <cuda_fp16.h>

#define TT 256
typedef unsigned int u32; typedef unsigned long long u64; typedef unsigned short u16;

// [mat 0..3][ih 0..1][p 0..3][kk 0..63][u 0..31][gate 0..3] half2(w_2kk, w_2kk+1)
__device__ __align__(16) __half2 g_W[262144];
__device__ __align__(16) __half2 g_OWp[8192];    // [p][kk][u]
__device__ float g_b[4][512];

__global__ void prep_kernel(
    const float* __restrict__ eW0, const float* __restrict__ eU0,
    const float* __restrict__ ebi0, const float* __restrict__ ebh0,
    const float* __restrict__ eW1, const float* __restrict__ eU1,
    const float* __restrict__ ebi1, const float* __restrict__ ebh1,
    const float* __restrict__ dW0, const float* __restrict__ dU0,
    const float* __restrict__ dbi0, const float* __restrict__ dbh0,
    const float* __restrict__ dW1, const float* __restrict__ dU1,
    const float* __restrict__ dbi1, const float* __restrict__ dbh1,
    const float* __restrict__ oW)
{
    int idx = blockIdx.x * 512 + threadIdx.x;
    int g = idx & 3, u = (idx >> 2) & 31, kk = (idx >> 7) & 63;
    int p = (idx >> 13) & 3, ih = (idx >> 15) & 1, mat = (idx >> 16) & 3;
    int sel = mat * 2 + ih;
    const float* M = (sel==0)?eW0:(sel==1)?eU0:(sel==2)?eW1:(sel==3)?eU1:
                     (sel==4)?dW0:(sel==5)?dU0:(sel==6)?dW1:dU1;
    int j = g * 128 + p * 32 + u;
    g_W[idx] = __floats2half2_rn(M[j*128 + 2*kk], M[j*128 + 2*kk + 1]);
    if (idx < 8192) {
        int d = (idx >> 11) * 32 + (idx & 31);
        int k2 = (idx >> 5) & 63;
        g_OWp[idx] = __floats2half2_rn(oW[d*128 + 2*k2], oW[d*128 + 2*k2 + 1]);
    }
    if (idx < 512) {
        g_b[0][idx] = ebi0[idx] + ebh0[idx];
        g_b[1][idx] = ebi1[idx] + ebh1[idx];
        g_b[2][idx] = dbi0[idx] + dbh0[idx];
        g_b[3][idx] = dbi1[idx] + dbh1[idx];
    }
}

__device__ __forceinline__ float sigf(float v)   { return 1.0f / (1.0f + __expf(-v)); }
__device__ __forceinline__ float tanhfa(float v) { return 1.0f - 2.0f / (__expf(2.0f * v) + 1.0f); }
__device__ __forceinline__ __half2 h2(u32 v) { return *(__half2*)&v; }
__device__ __forceinline__ u32 pk(float a, float b) {
    __half2 h = __floats2half2_rn(a, b); return *(u32*)&h;
}
__device__ __forceinline__ void spill(u64& acc, __half2 a) {
    float lo = __low2float(a), hi = __high2float(a);
    u64 q;
    asm("mov.b64 %0, {%1,%2};" : "=l"(q) : "f"(lo), "f"(hi));
    asm("add.rn.f32x2 %0, %1, %2;" : "=l"(acc) : "l"(acc), "l"(q));
}
__device__ __forceinline__ float fin2(u64 acc) {
    float lo, hi;
    asm("mov.b64 {%0,%1}, %2;" : "=f"(lo), "=f"(hi) : "l"(acc));
    return lo + hi;
}

// xh buffers: 4KB each parity, packed [sk(4)][rq(4)][kkl(16)][r4(4)] half2
__device__ __forceinline__ u32 xh_word(int k, int row) {
    int kk = k >> 1;
    return (u32)(((((kk >> 4) * 4 + (row >> 2)) * 16 + (kk & 15)) * 4) + (row & 3));
}

#define SW0I 0u
#define SW0H 32768u
#define SW1I 65536u
#define SW1H 98304u
#define SX   131072u
#define SH0  139264u
#define SH1  147456u
#define SOW  155648u
#define SRED0 163840u   // [s][gate][row][u] float = 32KB
#define SRED1 196608u   // 32KB
#define STOT  229376

#define CBAR() do { asm volatile("barrier.cluster.arrive.aligned;" ::: "memory"); \
                    asm volatile("barrier.cluster.wait.aligned;"   ::: "memory"); } while (0)

__device__ __forceinline__ void bc4(const u32* dsm, u32 off, u16 v) {
#pragma unroll
    for (int r = 0; r < 4; r++)
        asm volatile("st.shared::cluster.u16 [%0], %1;"
                     :: "r"(dsm[r] + off), "h"(v) : "memory");
}

__device__ __forceinline__ void stage_w(char* sm, int mat, int p, int tid) {
    const uint4* s0 = (const uint4*)g_W + ((mat*2+0)*4 + p) * 2048;
    const uint4* s1 = (const uint4*)g_W + ((mat*2+1)*4 + p) * 2048;
    uint4* d0 = (uint4*)(sm + (mat & 1) * 65536);
    uint4* d1 = (uint4*)(sm + (mat & 1) * 65536 + 32768);
#pragma unroll
    for (int i = 0; i < 4; i++) {
        d0[tid + i*512] = s0[tid + i*512];
        d1[tid + i*512] = s1[tid + i*512];
    }
}

// 4 rows x 4 gates over k-quarter s. g16[gate*4 + r].
__device__ __forceinline__ void gemm_r4(const char* sm, u32 wI, u32 wH,
    u32 xo, u32 ho, int u, int rg, int s, float* g16)
{
    const uint4* wi = (const uint4*)(sm + wI) + s*512 + u;
    const uint4* wh = (const uint4*)(sm + wH) + s*512 + u;
    const uint4* xr = (const uint4*)(sm + xo) + (s*4 + rg)*16;
    const uint4* hr = (const uint4*)(sm + ho) + (s*4 + rg)*16;
    u64 A[16];
#pragma unroll
    for (int i = 0; i < 16; i++) A[i] = 0;
#pragma unroll
    for (int c = 0; c < 4; c++) {
        __half2 a[16];
#pragma unroll
        for (int i = 0; i < 16; i++) a[i] = __float2half2_rn(0.f);
#pragma unroll
        for (int m = 0; m < 4; m++) {
            int kkl = c*4 + m;
            uint4 wq = wi[kkl*32];
            uint4 vq = wh[kkl*32];
            uint4 xq = xr[kkl];
            uint4 hq = hr[kkl];
#pragma unroll
            for (int r = 0; r < 4; r++) {
                __half2 xv = ((__half2*)&xq)[r];
                __half2 hv = ((__half2*)&hq)[r];
                a[r]    = __hfma2(h2(wq.x), xv, a[r]);
                a[4+r]  = __hfma2(h2(wq.y), xv, a[4+r]);
                a[8+r]  = __hfma2(h2(wq.z), xv, a[8+r]);
                a[12+r] = __hfma2(h2(wq.w), xv, a[12+r]);
                a[r]    = __hfma2(h2(vq.x), hv, a[r]);
                a[4+r]  = __hfma2(h2(vq.y), hv, a[4+r]);
                a[8+r]  = __hfma2(h2(vq.z), hv, a[8+r]);
                a[12+r] = __hfma2(h2(vq.w), hv, a[12+r]);
            }
        }
#pragma unroll
        for (int i = 0; i < 16; i++) spill(A[i], a[i]);
    }
#pragma unroll
    for (int i = 0; i < 16; i++) g16[i] = fin2(A[i]);
}

// all warps store partials: SRED[s][gate][rg*4+r][u]
__device__ __forceinline__ void red_store(char* sm, u32 base, int u, int rg, int s,
                                          const float* g16) {
    float* d = (float*)(sm + base) + u;
#pragma unroll
    for (int gate = 0; gate < 4; gate++)
#pragma unroll
        for (int r = 0; r < 4; r++)
            d[(((s*4 + gate) * 16) + rg*4 + r) * 32] = g16[gate*4 + r];
}

// thread (row, u): sum 4 k-slices per gate
__device__ __forceinline__ void red_gates(const char* sm, u32 base, int u, int row,
                                          float* g4) {
    const float* d = (const float*)(sm + base) + u;
#pragma unroll
    for (int gate = 0; gate < 4; gate++) {
        float v = d[((0*4 + gate)*16 + row) * 32];
        v += d[((1*4 + gate)*16 + row) * 32];
        v += d[((2*4 + gate)*16 + row) * 32];
        v += d[((3*4 + gate)*16 + row) * 32];
        g4[gate] = v;
    }
}

__global__ void __launch_bounds__(512, 1) __cluster_dims__(4, 1, 1)
lstm_main(const float* __restrict__ x, const float* __restrict__ out_b,
          float* __restrict__ out)
{
    extern __shared__ __align__(16) char sm[];
    const int tid = threadIdx.x;
    const int u = tid & 31, wid = tid >> 5;
    const int rg = wid & 3, s = wid >> 2;
    const int row = wid;                 // activation/projection row for this thread
    const int p  = blockIdx.x & 3;
    const int bg = (blockIdx.x >> 2) * 16;
    // byte offset of h(row, unit p*32+u) inside an xh buffer
    const u32 hb = (u32)((((p*4 + (row >> 2))*16 + (u >> 1))*16) + ((row & 3) << 2) + ((u & 1) << 1));

    u32 sb = (u32)__cvta_generic_to_shared(sm);
    u32 dsm[4];
#pragma unroll
    for (int r = 0; r < 4; r++)
        asm("mapa.shared::cluster.u32 %0, %1, %2;" : "=r"(dsm[r]) : "r"(sb), "r"(r));

    stage_w(sm, 0, p, tid);
    stage_w(sm, 1, p, tid);
#pragma unroll
    for (int i = 0; i < 3; i++)
        ((uint4*)(sm + SX))[tid + i*512] = make_uint4(0,0,0,0);   // X,H0,H1
    __syncthreads();
    if (tid < 256) {
        const int xr = tid >> 4, oct = tid & 15;
        const float* xp = x + ((size_t)(bg + xr) * TT) * 128 + oct * 8;
        float4 a = *(const float4*)xp, b = *(const float4*)(xp + 4);
        u32* X = (u32*)(sm + SX);
        X[xh_word(oct*8+0, xr)] = pk(a.x, a.y);
        X[xh_word(oct*8+2, xr)] = pk(a.z, a.w);
        X[xh_word(oct*8+4, xr)] = pk(b.x, b.y);
        X[xh_word(oct*8+6, xr)] = pk(b.z, b.w);
    }
    float bi0[4], bi1[4];
#pragma unroll
    for (int g = 0; g < 4; g++) {
        bi0[g] = g_b[0][g*128 + p*32 + u];
        bi1[g] = g_b[1][g*128 + p*32 + u];
    }
    float c0 = 0.f, c1 = 0.f;           // c-state of (row, u)
    float g16[16], g4[4];
    __syncthreads();
    CBAR();

    // -------------------- encoder: 1 CBAR / step --------------------
    for (int t = 0; t < TT; t++) {
        const u32 pt = (u32)(t & 1) * 4096u, pn = pt ^ 4096u;
        float4 xa, xb;
        const bool pre = (tid < 256) && (t < TT - 1);
        if (pre) {
            const float* xp = x + ((size_t)(bg + (tid >> 4)) * TT + t + 1) * 128 + (tid & 15) * 8;
            xa = *(const float4*)xp; xb = *(const float4*)(xp + 4);
        }
        gemm_r4(sm, SW0I, SW0H, SX + pt, SH0 + pt, u, rg, s, g16);
        red_store(sm, SRED0, u, rg, s, g16);
        __syncthreads();
        {
            red_gates(sm, SRED0, u, row, g4);
            float cn = sigf(g4[1] + bi0[1]) * c0 + sigf(g4[0] + bi0[0]) * tanhfa(g4[2] + bi0[2]);
            c0 = cn;
            float h = sigf(g4[3] + bi0[3]) * tanhfa(cn);
            bc4(dsm, SH0 + pn + hb, __half_as_ushort(__float2half(h)));
        }
        if (pre) {
            const int xr = tid >> 4, oct = tid & 15;
            u32* X = (u32*)(sm + SX + pn);
            X[xh_word(oct*8+0, xr)] = pk(xa.x, xa.y);
            X[xh_word(oct*8+2, xr)] = pk(xa.z, xa.w);
            X[xh_word(oct*8+4, xr)] = pk(xb.x, xb.y);
            X[xh_word(oct*8+6, xr)] = pk(xb.z, xb.w);
        }
        CBAR();
        gemm_r4(sm, SW1I, SW1H, SH0 + pn, SH1 + pt, u, rg, s, g16);
        red_store(sm, SRED1, u, rg, s, g16);
        __syncthreads();
        {
            red_gates(sm, SRED1, u, row, g4);
            float cn = sigf(g4[1] + bi1[1]) * c1 + sigf(g4[0] + bi1[0]) * tanhfa(g4[2] + bi1[2]);
            c1 = cn;
            float h = sigf(g4[3] + bi1[3]) * tanhfa(cn);
            bc4(dsm, SH1 + pn + hb, __half_as_ushort(__float2half(h)));
        }
        // SH1+pn consumed only after next step's CBAR
    }

    // -------------------- switch --------------------
    CBAR();
    if (tid < 256) {
        uint4 x0v = ((uint4*)(sm + SH1))[tid];         // final h1 (parity 0)
        ((uint4*)(sm + SX))[tid]  = x0v;
        ((uint4*)(sm + SH0))[tid] = make_uint4(0,0,0,0);
        ((uint4*)(sm + SH1))[tid] = make_uint4(0,0,0,0);
    }
    stage_w(sm, 2, p, tid);
    stage_w(sm, 3, p, tid);
    ((uint4*)(sm + SOW))[tid] = ((const uint4*)g_OWp)[p * 512 + tid];
#pragma unroll
    for (int g = 0; g < 4; g++) {
        bi0[g] = g_b[2][g*128 + p*32 + u];
        bi1[g] = g_b[3][g*128 + p*32 + u];
    }
    const float obv = out_b[p * 32 + u];
    c0 = 0.f; c1 = 0.f;
    __syncthreads();

    // -------------------- decoder: 2 CBARs / step --------------------
    const u32 pbase = (u32)((row >> 2) * 256 + (row & 3) * 4);
    for (int t = 0; t < TT; t++) {
        const u32 pt = (u32)(t & 1) * 4096u, pn = pt ^ 4096u;
        gemm_r4(sm, SW0I, SW0H, SX + pt, SH0 + pt, u, rg, s, g16);
        red_store(sm, SRED0, u, rg, s, g16);
        __syncthreads();
        {
            red_gates(sm, SRED0, u, row, g4);
            float cn = sigf(g4[1] + bi0[1]) * c0 + sigf(g4[0] + bi0[0]) * tanhfa(g4[2] + bi0[2]);
            c0 = cn;
            float h = sigf(g4[3] + bi0[3]) * tanhfa(cn);
            bc4(dsm, SH0 + pn + hb, __half_as_ushort(__float2half(h)));
        }
        CBAR();
        gemm_r4(sm, SW1I, SW1H, SH0 + pn, SH1 + pt, u, rg, s, g16);
        red_store(sm, SRED1, u, rg, s, g16);
        __syncthreads();
        {
            red_gates(sm, SRED1, u, row, g4);
            float cn = sigf(g4[1] + bi1[1]) * c1 + sigf(g4[0] + bi1[0]) * tanhfa(g4[2] + bi1[2]);
            c1 = cn;
            float h = sigf(g4[3] + bi1[3]) * tanhfa(cn);
            u16 hu = __half_as_ushort(__float2half(h));
            bc4(dsm, SH1 + pn + hb, hu);
            bc4(dsm, SX  + pn + hb, hu);
        }
        CBAR();
        {   // projection: thread -> (row, dim p*32+u)
            u64 P = 0;
            __half2 pa = __float2half2_rn(0.f);
            const char* hx = sm + SX + pn + pbase;
            const __half2* ow = (const __half2*)(sm + SOW) + u;
#pragma unroll 4
            for (int kk = 0; kk < 64; kk++) {
                __half2 hv = *(const __half2*)(hx + (kk >> 4)*1024 + (kk & 15)*16);
                pa = __hfma2(ow[kk*32], hv, pa);
                if ((kk & 15) == 15) { spill(P, pa); pa = __float2half2_rn(0.f); }
            }
            out[((size_t)(bg + row) * TT + t) * 128 + p * 32 + u] = fin2(P) + obv;
        }
    }
}

extern "C" void kernel_launch(void* const* d_in, const int* in_sizes, int n_in,
                              void* d_out, int out_size)
{
    cudaFuncSetAttribute(lstm_main, cudaFuncAttributeMaxDynamicSharedMemorySize, STOT);
    prep_kernel<<<512, 512>>>(
        (const float*)d_in[1],  (const float*)d_in[2],  (const float*)d_in[3],
        (const float*)d_in[4],  (const float*)d_in[5],  (const float*)d_in[6],
        (const float*)d_in[7],  (const float*)d_in[8],  (const float*)d_in[9],
        (const float*)d_in[10], (const float*)d_in[11], (const float*)d_in[12],
        (const float*)d_in[13], (const float*)d_in[14], (const float*)d_in[15],
        (const float*)d_in[16], (const float*)d_in[17]);
    lstm_main<<<128, 512, STOT>>>((const float*)d_in[0], (const float*)d_in[18],
                                  (float*)d_out);
}